// round 8
// baseline (speedup 1.0000x reference)
#include <cuda_runtime.h>

// RankCoxHazardLoss — B=512 rows, N=256. Sort-based, 256 thr/row (single wave).
// den = suffix scan; num_pairs = C(vcnt,2); pass2 (survival product) over the
// strict suffix j>k with packed f32x2 FMA/MUL (4 chains); rank violations over
// prefix j<k (4 chains). Last CTA reduces the per-row partials to the scalar.

#define EPSF 1e-7f
static constexpr int BB = 512;
static constexpr int NN = 256;

__device__ float g_row_cox[BB];
__device__ float g_row_vb[BB];
__device__ float g_row_rank[BB];
__device__ unsigned int g_done = 0;

__device__ __forceinline__ unsigned long long pack2(float a, float b) {
    unsigned long long r;
    asm("mov.b64 %0, {%1, %2};" : "=l"(r) : "f"(a), "f"(b));
    return r;
}
__device__ __forceinline__ unsigned long long fma2(
    unsigned long long a, unsigned long long b, unsigned long long c) {
    unsigned long long d;
    asm("fma.rn.f32x2 %0, %1, %2, %3;" : "=l"(d) : "l"(a), "l"(b), "l"(c));
    return d;
}
__device__ __forceinline__ unsigned long long mul2(
    unsigned long long a, unsigned long long b) {
    unsigned long long d;
    asm("mul.rn.f32x2 %0, %1, %2;" : "=l"(d) : "l"(a), "l"(b));
    return d;
}
__device__ __forceinline__ void unpack2(unsigned long long v, float& lo, float& hi) {
    asm("mov.b64 {%0, %1}, %2;" : "=f"(lo), "=f"(hi) : "l"(v));
}

__global__ __launch_bounds__(NN) void fused_kernel(
    const float* __restrict__ pred,
    const float* __restrict__ target,
    const void*  __restrict__ validp,
    float*       __restrict__ out)
{
    __shared__ __align__(16) unsigned int s_key[NN];
    __shared__ __align__(16) float s_e2[NN];   // exp(pred), sorted
    __shared__ __align__(16) float s_rz[NN];   // valid ? exp(-pred) : 0, sorted
    __shared__ __align__(16) float s_t2[NN];   // masked time, sorted
    __shared__ float s_w0[8], s_w1[8];
    __shared__ int   s_vc[8];
    __shared__ unsigned int s_islast;

    const int tid  = threadIdx.x;
    const int lane = tid & 31;
    const int wid  = tid >> 5;
    const int b    = blockIdx.x;
    const int idx  = b * NN + tid;

    // ---- valid_mask dtype detection (bit patterns of first 256 words) ----
    const unsigned int w = ((const unsigned int*)validp)[tid];
    const int any_bf = __syncthreads_or((w == 0x3F803F80u) || (w == 0x00003F80u));
    const int any_f  = __syncthreads_or(w == 0x3F800000u);
    const int any_mb = __syncthreads_or((w & 0xFFFFFF00u) != 0u &&
                                        w != 0x3F800000u && w != 0x3F803F80u &&
                                        w != 0x00003F80u);
    bool v_i;
    if (any_bf)      v_i = ((const unsigned short*)validp)[idx] != 0;
    else if (any_f)  v_i = ((const float*)validp)[idx] != 0.0f;
    else if (any_mb) v_i = ((const unsigned char*)validp)[idx] != 0;
    else             v_i = ((const int*)validp)[idx] != 0;

    const float p_i  = pred[idx];
    const float t_i  = target[idx];
    const float tm_i = v_i ? t_i : -1.0f;

    // unique sortable key: ordered float bits, low 8 bits = index
    unsigned int u = __float_as_uint(tm_i);
    u ^= (unsigned int)((int)u >> 31) | 0x80000000u;
    const unsigned int key = (u & 0xFFFFFF00u) | (unsigned int)tid;
    s_key[tid] = key;

    const unsigned int bal = __ballot_sync(0xffffffffu, v_i);
    if (lane == 0) s_vc[wid] = __popc(bal);
    __syncthreads();
    int vcnt = 0;
    #pragma unroll
    for (int k2 = 0; k2 < 8; k2++) vcnt += s_vc[k2];
    const int ninv = NN - vcnt;

    // ---- rank = #{key_j < key_i}, 4 independent counters ----
    const uint4* k4 = (const uint4*)s_key;
    int r0 = 0, r1 = 0, r2 = 0, r3 = 0;
    #pragma unroll 16
    for (int q = 0; q < NN / 4; q++) {
        const uint4 kk = k4[q];
        r0 += (kk.x < key); r1 += (kk.y < key);
        r2 += (kk.z < key); r3 += (kk.w < key);
    }
    const int rank = (r0 + r1) + (r2 + r3);

    // ---- scatter to sorted order ----
    s_e2[rank] = __expf(p_i);
    s_rz[rank] = v_i ? __expf(-p_i) : 0.0f;
    s_t2[rank] = tm_i;
    __syncthreads();

    const int   k   = tid;            // sorted slot owned by this thread
    const float E_k = s_e2[k];
    const float T_k = s_t2[k];
    const float bmax = s_t2[NN - 1];

    // ---- den_k = suffix sum of E over [k, 255] ----
    float sfx = E_k;
    #pragma unroll
    for (int o = 1; o < 32; o <<= 1) {
        const float t = __shfl_down_sync(0xffffffffu, sfx, o);
        if (lane + o < 32) sfx += t;
    }
    if (lane == 0) s_w0[wid] = sfx;
    __syncthreads();
    float den = sfx;
    #pragma unroll
    for (int k2 = 7; k2 > 0; k2--) if (k2 > wid) den += s_w0[k2];
    const float invden = 1.0f / den;

    const int qb = k >> 2;       // boundary quad index
    const int kc = k & 3;        // position within boundary quad

    // ---- rank violations over prefix j<k: 4 chains, then boundary ----
    const float4* e4 = (const float4*)s_e2;
    const float4* z4 = (const float4*)s_rz;
    float rs0 = 0.0f, rs1 = 0.0f, rs2 = 0.0f, rs3 = 0.0f;
    #pragma unroll 8
    for (int q = 0; q < qb; q++) {
        const float4 E = e4[q];
        const float4 Z = z4[q];
        if (E.x < E_k) rs0 += Z.x;
        if (E.y < E_k) rs1 += Z.y;
        if (E.z < E_k) rs2 += Z.z;
        if (E.w < E_k) rs3 += Z.w;
    }
    {   // boundary quad: pairs j = 4*qb + c with c < kc
        const float4 E = e4[qb];
        const float4 Z = z4[qb];
        if (0 < kc && E.x < E_k) rs0 += Z.x;
        if (1 < kc && E.y < E_k) rs1 += Z.y;
        if (2 < kc && E.z < E_k) rs2 += Z.z;
    }
    const float rs = (rs0 + rs1) + (rs2 + rs3);

    // ---- pass 2: survival product over strict suffix j>k ----
    // term_j = (1+eps) - E_j/den_k  (clamp provably never fires for j>k)
    const float c1c = 1.0f + EPSF;
    float pdx = 1.0f;
    {   // boundary quad: pairs j = 4*qb + c with c > kc
        const float4 E = e4[qb];
        if (0 > kc) pdx *= fmaf(-E.x, invden, c1c);
        if (1 > kc) pdx *= fmaf(-E.y, invden, c1c);
        if (2 > kc) pdx *= fmaf(-E.z, invden, c1c);
        pdx *= fmaf(-E.w, invden, c1c);   // kc<=3 always -> c=3 included unless kc==3
        if (3 == kc) pdx = 1.0f, pdx *= 1.0f;  // undo if c==kc  (see below)
    }
    // NOTE: the line above would be wrong; use exact form instead:
    {
        const float4 E = e4[qb];
        float t = 1.0f;
        if (0 > kc) t *= fmaf(-E.x, invden, c1c);
        if (1 > kc) t *= fmaf(-E.y, invden, c1c);
        if (2 > kc) t *= fmaf(-E.z, invden, c1c);
        if (3 > kc) t *= fmaf(-E.w, invden, c1c);
        pdx = t;
    }
    const unsigned long long ninv2 = pack2(-invden, -invden);
    const unsigned long long c1c2  = pack2(c1c, c1c);
    const unsigned long long one2  = pack2(1.0f, 1.0f);
    unsigned long long pdA = one2, pdB = one2, pdC = one2, pdD = one2;
    const ulonglong2* e8 = (const ulonglong2*)s_e2;
    int q = qb + 1;
    for (; q + 1 < NN / 4; q += 2) {           // 16 floats per iteration
        const ulonglong2 Ea = e8[q];
        const ulonglong2 Eb = e8[q + 1];
        pdA = mul2(pdA, fma2(Ea.x, ninv2, c1c2));
        pdB = mul2(pdB, fma2(Ea.y, ninv2, c1c2));
        pdC = mul2(pdC, fma2(Eb.x, ninv2, c1c2));
        pdD = mul2(pdD, fma2(Eb.y, ninv2, c1c2));
    }
    if (q < NN / 4) {
        const ulonglong2 Ea = e8[q];
        pdA = mul2(pdA, fma2(Ea.x, ninv2, c1c2));
        pdB = mul2(pdB, fma2(Ea.y, ninv2, c1c2));
    }
    pdA = mul2(pdA, pdC);
    pdB = mul2(pdB, pdD);
    float a0, a1, b0, b1;
    unpack2(pdA, a0, a1);
    unpack2(pdB, b0, b1);
    const float prod = pdx * ((a0 * a1) * (b0 * b1));

    // ---- finalize per sorted slot ----
    const bool valid_k = (k >= ninv);
    const bool elim = valid_k && (T_k > 0.0f) && (T_k < bmax);
    float loss = 0.0f;
    if (elim)
        loss = (__logf(den) - __logf(E_k)) - __logf(prod);
    float rankc = valid_k ? E_k * rs : 0.0f;

    // ---- block reduce (loss, rankc) ----
    #pragma unroll
    for (int o = 16; o; o >>= 1) {
        loss  += __shfl_xor_sync(0xffffffffu, loss, o);
        rankc += __shfl_xor_sync(0xffffffffu, rankc, o);
    }
    __syncthreads();                       // s_w0 reuse
    if (lane == 0) { s_w0[wid] = loss; s_w1[wid] = rankc; }
    __syncthreads();
    if (tid == 0) {
        float tl = 0.0f, tr = 0.0f;
        #pragma unroll
        for (int k2 = 0; k2 < 8; k2++) { tl += s_w0[k2]; tr += s_w1[k2]; }
        const float fv = (float)vcnt;
        const float npairs = 0.5f * fv * (fv - 1.0f);   // C(vcnt,2)
        const float vb = (vcnt >= 2) ? 1.0f : 0.0f;
        g_row_cox[b]  = vb * tl;
        g_row_vb[b]   = vb;
        g_row_rank[b] = tr / fmaxf(npairs, 1.0f);
        __threadfence();
        const unsigned int t = atomicAdd(&g_done, 1u);
        s_islast = (t == (unsigned int)(BB - 1)) ? 1u : 0u;
    }
    __syncthreads();

    // ---- last block: final scalar reduction over 512 rows ----
    if (s_islast) {
        float c = g_row_cox[tid]  + g_row_cox[tid + NN];
        float v = g_row_vb[tid]   + g_row_vb[tid + NN];
        float r = g_row_rank[tid] + g_row_rank[tid + NN];
        #pragma unroll
        for (int o = 16; o; o >>= 1) {
            c += __shfl_xor_sync(0xffffffffu, c, o);
            v += __shfl_xor_sync(0xffffffffu, v, o);
            r += __shfl_xor_sync(0xffffffffu, r, o);
        }
        __syncthreads();
        if (lane == 0) { s_w0[wid] = c; s_w1[wid] = v; ((float*)s_vc)[wid] = r; }
        __syncthreads();
        if (tid == 0) {
            float C = 0.0f, V = 0.0f, R = 0.0f;
            #pragma unroll
            for (int k2 = 0; k2 < 8; k2++) {
                C += s_w0[k2]; V += s_w1[k2]; R += ((float*)s_vc)[k2];
            }
            out[0] = C / fmaxf(V, 1.0f) + R * (1.0f / (float)BB);
            g_done = 0;   // reset for next graph replay
        }
    }
}

extern "C" void kernel_launch(void* const* d_in, const int* in_sizes, int n_in,
                              void* d_out, int out_size)
{
    const float* pred   = (const float*)d_in[0];
    const float* target = (const float*)d_in[1];
    const void*  valid  = (const void*)d_in[2];
    float*       out    = (float*)d_out;

    fused_kernel<<<BB, NN>>>(pred, target, valid, out);
}

// round 9
// speedup vs baseline: 1.2516x; 1.2516x over previous
#include <cuda_runtime.h>

// RankCoxHazardLoss — B=512 rows, N=256. Sort-based, 256 thr/row.
// Rank via warp-bitonic sort (shfl) + 8x branchless binary search in SMEM runs
// (replaces the O(N) per-thread brute-force count). den = suffix scan;
// num_pairs = C(vcnt,2); pass2 over strict suffix j>k with packed f32x2;
// rank violations over prefix j<k. Last CTA reduces to the scalar.

#define EPSF 1e-7f
static constexpr int BB = 512;
static constexpr int NN = 256;

__device__ float g_row_cox[BB];
__device__ float g_row_vb[BB];
__device__ float g_row_rank[BB];
__device__ unsigned int g_done = 0;

__device__ __forceinline__ unsigned long long pack2(float a, float b) {
    unsigned long long r;
    asm("mov.b64 %0, {%1, %2};" : "=l"(r) : "f"(a), "f"(b));
    return r;
}
__device__ __forceinline__ unsigned long long fma2(
    unsigned long long a, unsigned long long b, unsigned long long c) {
    unsigned long long d;
    asm("fma.rn.f32x2 %0, %1, %2, %3;" : "=l"(d) : "l"(a), "l"(b), "l"(c));
    return d;
}
__device__ __forceinline__ unsigned long long mul2(
    unsigned long long a, unsigned long long b) {
    unsigned long long d;
    asm("mul.rn.f32x2 %0, %1, %2;" : "=l"(d) : "l"(a), "l"(b));
    return d;
}
__device__ __forceinline__ void unpack2(unsigned long long v, float& lo, float& hi) {
    asm("mov.b64 {%0, %1}, %2;" : "=f"(lo), "=f"(hi) : "l"(v));
}

__global__ __launch_bounds__(NN) void fused_kernel(
    const float* __restrict__ pred,
    const float* __restrict__ target,
    const void*  __restrict__ validp,
    float*       __restrict__ out)
{
    __shared__ __align__(16) unsigned int s_key[NN];  // sorted runs (32/warp)
    __shared__ int   s_rnk[NN];                       // rank by item index
    __shared__ __align__(16) float s_e2[NN];   // exp(pred), sorted
    __shared__ __align__(16) float s_rz[NN];   // valid ? 1/exp(pred) : 0, sorted
    __shared__ __align__(16) float s_t2[NN];   // masked time, sorted
    __shared__ float s_w0[8], s_w1[8];
    __shared__ int   s_vc[8];
    __shared__ unsigned int s_islast;

    const int tid  = threadIdx.x;
    const int lane = tid & 31;
    const int wid  = tid >> 5;
    const int b    = blockIdx.x;
    const int idx  = b * NN + tid;

    // ---- valid_mask dtype detection (bit patterns of first 256 words) ----
    const unsigned int w = ((const unsigned int*)validp)[tid];
    const int any_bf = __syncthreads_or((w == 0x3F803F80u) || (w == 0x00003F80u));
    const int any_f  = __syncthreads_or(w == 0x3F800000u);
    const int any_mb = __syncthreads_or((w & 0xFFFFFF00u) != 0u &&
                                        w != 0x3F800000u && w != 0x3F803F80u &&
                                        w != 0x00003F80u);
    bool v_i;
    if (any_bf)      v_i = ((const unsigned short*)validp)[idx] != 0;
    else if (any_f)  v_i = ((const float*)validp)[idx] != 0.0f;
    else if (any_mb) v_i = ((const unsigned char*)validp)[idx] != 0;
    else             v_i = ((const int*)validp)[idx] != 0;

    const float p_i  = pred[idx];
    const float t_i  = target[idx];
    const float tm_i = v_i ? t_i : -1.0f;

    // unique sortable key: ordered float bits, low 8 bits = item index
    unsigned int u = __float_as_uint(tm_i);
    u ^= (unsigned int)((int)u >> 31) | 0x80000000u;
    const unsigned int key = (u & 0xFFFFFF00u) | (unsigned int)tid;

    const unsigned int bal = __ballot_sync(0xffffffffu, v_i);
    if (lane == 0) s_vc[wid] = __popc(bal);

    // ---- warp bitonic sort (ascending by lane) of the 32 keys ----
    unsigned int v = key;
    #pragma unroll
    for (int kk = 2; kk <= 32; kk <<= 1) {
        #pragma unroll
        for (int j = kk >> 1; j > 0; j >>= 1) {
            const unsigned int o = __shfl_xor_sync(0xffffffffu, v, j);
            const bool takeMin = (((lane & kk) == 0) == ((lane & j) == 0));
            v = takeMin ? umin(v, o) : umax(v, o);
        }
    }
    s_key[wid * 32 + lane] = v;
    __syncthreads();

    // ---- global rank of v: sum of lower_bounds over all 8 sorted runs ----
    int rank = 0;
    #pragma unroll
    for (int w2 = 0; w2 < 8; w2++) {
        const unsigned int* run = s_key + w2 * 32;
        int c = 0;
        if (run[c + 15] < v) c += 16;
        if (run[c + 7]  < v) c += 8;
        if (run[c + 3]  < v) c += 4;
        if (run[c + 1]  < v) c += 2;
        if (run[c]      < v) c += 1;
        if (run[c]      < v) c += 1;   // fixup probe (count may be 32)
        rank += c;
    }
    s_rnk[v & 0xFFu] = rank;     // route rank back to owning item
    __syncthreads();

    int vcnt = 0;
    #pragma unroll
    for (int k2 = 0; k2 < 8; k2++) vcnt += s_vc[k2];
    const int ninv = NN - vcnt;

    // ---- scatter to sorted order ----
    const int myrank = s_rnk[tid];
    const float e_i  = __expf(p_i);
    s_e2[myrank] = e_i;
    s_rz[myrank] = v_i ? __frcp_rn(e_i) : 0.0f;
    s_t2[myrank] = tm_i;
    __syncthreads();

    const int   k   = tid;            // sorted slot owned by this thread
    const float E_k = s_e2[k];
    const float T_k = s_t2[k];
    const float bmax = s_t2[NN - 1];

    // ---- den_k = suffix sum of E over [k, 255] ----
    float sfx = E_k;
    #pragma unroll
    for (int o = 1; o < 32; o <<= 1) {
        const float t = __shfl_down_sync(0xffffffffu, sfx, o);
        if (lane + o < 32) sfx += t;
    }
    if (lane == 0) s_w0[wid] = sfx;
    __syncthreads();
    float den = sfx;
    #pragma unroll
    for (int k2 = 7; k2 > 0; k2--) if (k2 > wid) den += s_w0[k2];
    const float invden = 1.0f / den;

    const int qb = k >> 2;       // boundary quad index
    const int kc = k & 3;        // position within boundary quad

    // ---- rank violations over prefix j<k: full quads [0,qb), then boundary ----
    const float4* e4 = (const float4*)s_e2;
    const float4* z4 = (const float4*)s_rz;
    float rs = 0.0f;
    #pragma unroll 4
    for (int q = 0; q < qb; q++) {
        const float4 E = e4[q];
        const float4 Z = z4[q];
        if (E.x < E_k) rs += Z.x;
        if (E.y < E_k) rs += Z.y;
        if (E.z < E_k) rs += Z.z;
        if (E.w < E_k) rs += Z.w;
    }
    {   // boundary quad: pairs j = 4*qb + c with c < kc
        const float4 E = e4[qb];
        const float4 Z = z4[qb];
        if (0 < kc && E.x < E_k) rs += Z.x;
        if (1 < kc && E.y < E_k) rs += Z.y;
        if (2 < kc && E.z < E_k) rs += Z.z;
    }

    // ---- pass 2: survival product over strict suffix j>k ----
    // term_j = (1+eps) - E_j/den_k  (clamp provably never fires for j>k)
    const float c1c = 1.0f + EPSF;
    float pdx = 1.0f;
    {   // boundary quad: pairs j = 4*qb + c with c > kc
        const float4 E = e4[qb];
        if (0 > kc) pdx *= fmaf(-E.x, invden, c1c);
        if (1 > kc) pdx *= fmaf(-E.y, invden, c1c);
        if (2 > kc) pdx *= fmaf(-E.z, invden, c1c);
        if (3 > kc) pdx *= fmaf(-E.w, invden, c1c);
    }
    const unsigned long long ninv2 = pack2(-invden, -invden);
    const unsigned long long c1c2  = pack2(c1c, c1c);
    unsigned long long pdA = pack2(1.0f, 1.0f);
    unsigned long long pdB = pdA;
    const ulonglong2* e8 = (const ulonglong2*)s_e2;
    #pragma unroll 4
    for (int q = qb + 1; q < NN / 4; q++) {
        const ulonglong2 E2 = e8[q];
        pdA = mul2(pdA, fma2(E2.x, ninv2, c1c2));
        pdB = mul2(pdB, fma2(E2.y, ninv2, c1c2));
    }
    float a0, a1, b0, b1;
    unpack2(pdA, a0, a1);
    unpack2(pdB, b0, b1);
    const float prod = pdx * ((a0 * a1) * (b0 * b1));

    // ---- finalize per sorted slot ----
    const bool valid_k = (k >= ninv);
    const bool elim = valid_k && (T_k > 0.0f) && (T_k < bmax);
    float loss = 0.0f;
    if (elim)
        loss = __logf(den / (E_k * prod));   // = log den - log E_k - log prod
    float rankc = valid_k ? E_k * rs : 0.0f;

    // ---- block reduce (loss, rankc) ----
    #pragma unroll
    for (int o = 16; o; o >>= 1) {
        loss  += __shfl_xor_sync(0xffffffffu, loss, o);
        rankc += __shfl_xor_sync(0xffffffffu, rankc, o);
    }
    __syncthreads();                       // s_w0 reuse
    if (lane == 0) { s_w0[wid] = loss; s_w1[wid] = rankc; }
    __syncthreads();
    if (tid == 0) {
        float tl = 0.0f, tr = 0.0f;
        #pragma unroll
        for (int k2 = 0; k2 < 8; k2++) { tl += s_w0[k2]; tr += s_w1[k2]; }
        const float fv = (float)vcnt;
        const float npairs = 0.5f * fv * (fv - 1.0f);   // C(vcnt,2)
        const float vb = (vcnt >= 2) ? 1.0f : 0.0f;
        g_row_cox[b]  = vb * tl;
        g_row_vb[b]   = vb;
        g_row_rank[b] = tr / fmaxf(npairs, 1.0f);
        __threadfence();
        const unsigned int t = atomicAdd(&g_done, 1u);
        s_islast = (t == (unsigned int)(BB - 1)) ? 1u : 0u;
    }
    __syncthreads();

    // ---- last block: final scalar reduction over 512 rows ----
    if (s_islast) {
        float c = g_row_cox[tid]  + g_row_cox[tid + NN];
        float v2 = g_row_vb[tid]  + g_row_vb[tid + NN];
        float r = g_row_rank[tid] + g_row_rank[tid + NN];
        #pragma unroll
        for (int o = 16; o; o >>= 1) {
            c  += __shfl_xor_sync(0xffffffffu, c, o);
            v2 += __shfl_xor_sync(0xffffffffu, v2, o);
            r  += __shfl_xor_sync(0xffffffffu, r, o);
        }
        __syncthreads();
        if (lane == 0) { s_w0[wid] = c; s_w1[wid] = v2; ((float*)s_vc)[wid] = r; }
        __syncthreads();
        if (tid == 0) {
            float C = 0.0f, V = 0.0f, R = 0.0f;
            #pragma unroll
            for (int k2 = 0; k2 < 8; k2++) {
                C += s_w0[k2]; V += s_w1[k2]; R += ((float*)s_vc)[k2];
            }
            out[0] = C / fmaxf(V, 1.0f) + R * (1.0f / (float)BB);
            g_done = 0;   // reset for next graph replay
        }
    }
}

extern "C" void kernel_launch(void* const* d_in, const int* in_sizes, int n_in,
                              void* d_out, int out_size)
{
    const float* pred   = (const float*)d_in[0];
    const float* target = (const float*)d_in[1];
    const void*  valid  = (const void*)d_in[2];
    float*       out    = (float*)d_out;

    fused_kernel<<<BB, NN>>>(pred, target, valid, out);
}